// round 10
// baseline (speedup 1.0000x reference)
#include <cuda_runtime.h>

#define TPB  256
#define PPT  4
#define TILE (TPB * PPT)   // 1024 points per block

// Record table: 7x7 grid (indices (ci+1)*7+(cj+1)), border slots = sentinel
// shapes that are never "inside". 5 float4 per record:
//  v0: ax, ay, bx, by
//  v1: cx, cy, d0x(=bx-ax), d0y(=by-ay)
//  v2: d1x(=cx-bx), d1y(=cy-by), d2x(=ax-cx), d2y(=ay-cy)
//  v3: ocx, ocy, r2, ecx
//  v4: ecy, 1/erx, 1/ery, c3 (shape base index *3, as int bits)

// Shade one record, update best. Exact reference op order (no fma contraction).
#define SHADE_CELL(rr)                                                         \
    do {                                                                       \
        int _r = (rr);                                                         \
        float4 v0 = rec[_r * 5 + 0];                                           \
        float4 v1 = rec[_r * 5 + 1];                                           \
        float4 v2 = rec[_r * 5 + 2];                                           \
        float4 v3 = rec[_r * 5 + 3];                                           \
        float4 v4 = rec[_r * 5 + 4];                                           \
        float e0 = __fsub_rn(__fmul_rn(__fsub_rn(px, v0.x), v1.w),             \
                             __fmul_rn(__fsub_rn(py, v0.y), v1.z));            \
        float e1 = __fsub_rn(__fmul_rn(__fsub_rn(px, v0.z), v2.y),             \
                             __fmul_rn(__fsub_rn(py, v0.w), v2.x));            \
        float e2 = __fsub_rn(__fmul_rn(__fsub_rn(px, v1.x), v2.w),             \
                             __fmul_rn(__fsub_rn(py, v1.y), v2.z));            \
        float emin = fminf(fminf(e0, e1), e2);                                 \
        float emax = fmaxf(fmaxf(e0, e1), e2);                                 \
        bool tri_in = (emin >= 0.0f) || (emax <= 0.0f);                        \
        float dxc = __fsub_rn(px, v3.x), dyc = __fsub_rn(py, v3.y);            \
        bool circ_in =                                                         \
            __fadd_rn(__fmul_rn(dxc, dxc), __fmul_rn(dyc, dyc)) <= v3.z;       \
        float xn = __fmul_rn(__fsub_rn(px, v3.w), v4.y);                       \
        float yn = __fmul_rn(__fsub_rn(py, v4.x), v4.z);                       \
        bool ell_in =                                                          \
            __fadd_rn(__fmul_rn(xn, xn), __fmul_rn(yn, yn)) <= 1.0f;           \
        int c3 = __float_as_int(v4.w);                                         \
        int cb = tri_in ? c3 : -1;                                             \
        cb = circ_in ? c3 + 1 : cb;                                            \
        cb = ell_in ? c3 + 2 : cb;                                             \
        best = best > cb ? best : cb;                                          \
    } while (0)

__global__ __launch_bounds__(TPB)
void vg_kernel(const float* __restrict__ x, const float* __restrict__ p,
               float* __restrict__ out, int n)
{
    __shared__ float4 rec[49 * 5];
    __shared__ float  colors[76 * 3];      // slot 0 = black
    __shared__ float2 sp[TILE];            // (cell,quadrant)-sorted points
    __shared__ unsigned int stmp[TILE];    // key | rank<<8 | meta<<18
    __shared__ unsigned int sinfo[TILE];   // orig | meta<<10
    __shared__ unsigned char sbest[TILE];  // winner+1 per ORIGINAL point
    __shared__ int hist[225];
    __shared__ int off[225];
    __shared__ int wsum[8];

    const int tid = threadIdx.x;

    if (tid < 49) {
        int i = tid / 7 - 1, j = tid % 7 - 1;
        bool real = ((unsigned)i <= 4u) && ((unsigned)j <= 4u);
        if (real) {
            const float* q = p + (i * 5 + j) * 28;
            float ax = q[1], ay = q[2], bx = q[3], by = q[4], cx = q[5], cy = q[6];
            rec[tid * 5 + 0] = make_float4(ax, ay, bx, by);
            rec[tid * 5 + 1] = make_float4(cx, cy, __fsub_rn(bx, ax), __fsub_rn(by, ay));
            rec[tid * 5 + 2] = make_float4(__fsub_rn(cx, bx), __fsub_rn(cy, by),
                                           __fsub_rn(ax, cx), __fsub_rn(ay, cy));
            float ocx = q[12], ocy = q[13], r = q[14];
            float ecx = q[20], ecy = q[21], erx = q[22], ery = q[23];
            rec[tid * 5 + 3] = make_float4(ocx, ocy, __fmul_rn(r, r), ecx);
            rec[tid * 5 + 4] = make_float4(ecy, 1.0f / erx, 1.0f / ery,
                                           __int_as_float((i * 5 + j) * 3));
        } else {
            // Sentinel: tri edges give e0<0, e1>0 (mixed -> outside);
            // circle r2=-1; ellipse center at 1e9.
            rec[tid * 5 + 0] = make_float4(1e9f, 0.0f, 1e9f, 0.0f);
            rec[tid * 5 + 1] = make_float4(0.0f, 0.0f, 0.0f, 1.0f);   // d0=(0,1)
            rec[tid * 5 + 2] = make_float4(0.0f, -1.0f, 0.0f, 0.0f);  // d1=(0,-1), d2=0
            rec[tid * 5 + 3] = make_float4(0.0f, 0.0f, -1.0f, 1e9f);
            rec[tid * 5 + 4] = make_float4(0.0f, 1.0f, 1.0f, __int_as_float(0));
        }
    }
    for (int idx = tid; idx < 228; idx += TPB) {
        if (idx < 3) colors[idx] = 0.0f;
        else {
            int s = (idx - 3) / 3, k = (idx - 3) % 3;
            int c = s / 3, t = s % 3;
            int o = (t == 0) ? (8 + k) : ((t == 1) ? (16 + k) : (25 + k));
            colors[idx] = p[c * 28 + o];
        }
    }
    if (tid < 225) hist[tid] = 0;
    __syncthreads();

    const int base = blockIdx.x * TILE;

    // ---- Phase 1: load points, integer classify, histogram ----
    float2 pts[PPT];
#pragma unroll
    for (int k = 0; k < PPT; k++) {
        int li = k * TPB + tid;
        int gi = base + li;
        float2 pt = (gi < n) ? ((const float2*)x)[gi] : make_float2(0.5f, 0.5f);
        pts[k] = pt;
        // s in 1/16-cell units; thresholds f16<=6 (<0.4375) / f16>=9 (>=0.5625)
        // bracket the true 0.4 shape overhang with >=0.0375 cell-width margin.
        int sx = (int)(pt.x * 80.0f); sx = sx < 0 ? 0 : (sx > 79 ? 79 : sx);
        int sy = (int)(pt.y * 80.0f); sy = sy < 0 ? 0 : (sy > 79 ? 79 : sy);
        int ci = sx >> 4, fx = sx & 15;
        int cj = sy >> 4, fy = sy & 15;
        int dxp = (fx <= 6) ? 0 : ((fx >= 9) ? 2 : 1);   // dxn+1
        int dyp = (fy <= 6) ? 0 : ((fy >= 9) ? 2 : 1);   // dyn+1
        int cc = ci * 5 + cj;
        int key = cc * 9 + dxp * 3 + dyp;                // 0..224
        unsigned meta = (unsigned)(ci * 7 + cj + 8) |    // rp = (ci+1)*7+(cj+1)
                        ((unsigned)dxp << 6) | ((unsigned)dyp << 8);
        int rank = atomicAdd(&hist[key], 1);
        stmp[li] = (unsigned)key | ((unsigned)rank << 8) | (meta << 18);
    }
    __syncthreads();

    // ---- Phase 2: exclusive scan of 225 bins (two-level shuffle scan) ----
    {
        int v = (tid < 225) ? hist[tid] : 0;
        int s = v;
#pragma unroll
        for (int d = 1; d < 32; d <<= 1) {
            int t = __shfl_up_sync(0xffffffff, s, d);
            if ((tid & 31) >= d) s += t;
        }
        if ((tid & 31) == 31) wsum[tid >> 5] = s;
        __syncthreads();
        if (tid < 8) {
            int w = wsum[tid];
            int sw = w;
#pragma unroll
            for (int d = 1; d < 8; d <<= 1) {
                int t = __shfl_up_sync(0xff, sw, d);
                if (tid >= d) sw += t;
            }
            wsum[tid] = sw - w;
        }
        __syncthreads();
        if (tid < 225) off[tid] = (s - v) + wsum[tid >> 5];
    }
    __syncthreads();

    // ---- Phase 3: scatter into (cell,quadrant)-sorted order ----
#pragma unroll
    for (int k = 0; k < PPT; k++) {
        int li = k * TPB + tid;
        unsigned m = stmp[li];
        int pos = off[m & 255] + (int)((m >> 8) & 1023);
        sp[pos]    = pts[k];
        sinfo[pos] = (unsigned)li | ((m >> 18) << 10);
    }
    __syncthreads();

    // ---- Phase 4: uniform 4-record shading (no clamps, no validity) ----
#pragma unroll 1
    for (int k = 0; k < PPT; k++) {
        int li = k * TPB + tid;
        float2 pt = sp[li];
        const float px = pt.x, py = pt.y;
        unsigned m = sinfo[li];
        int orig = m & 1023;
        int rp   = (m >> 10) & 63;
        int dxn  = (int)((m >> 16) & 3) - 1;
        int dyn  = (int)((m >> 18) & 3) - 1;
        int rx   = rp + dxn * 7;
        int ry   = rp + dyn;
        int rxy  = rx + dyn;

        int best = -1;
        SHADE_CELL(rp);
        SHADE_CELL(rx);
        SHADE_CELL(ry);
        SHADE_CELL(rxy);

        sbest[orig] = (unsigned char)(best + 1);
    }
    __syncthreads();

    // ---- Phase 5: vectorized output (3 x STG.128 per thread) ----
    {
        int gi0 = base + tid * 4;
        if (gi0 + 4 <= n) {
            uchar4 u = *(const uchar4*)(sbest + tid * 4);
            int b0 = (int)u.x * 3, b1 = (int)u.y * 3;
            int b2 = (int)u.z * 3, b3 = (int)u.w * 3;
            float4 o0 = make_float4(colors[b0], colors[b0 + 1], colors[b0 + 2],
                                    colors[b1]);
            float4 o1 = make_float4(colors[b1 + 1], colors[b1 + 2],
                                    colors[b2], colors[b2 + 1]);
            float4 o2 = make_float4(colors[b2 + 2], colors[b3],
                                    colors[b3 + 1], colors[b3 + 2]);
            float4* dst = (float4*)(out + (size_t)gi0 * 3);
            dst[0] = o0; dst[1] = o1; dst[2] = o2;
        } else {
            for (int k = 0; k < 4; k++) {
                int gi = gi0 + k;
                if (gi < n) {
                    int cb = (int)sbest[tid * 4 + k] * 3;
                    out[gi * 3 + 0] = colors[cb + 0];
                    out[gi * 3 + 1] = colors[cb + 1];
                    out[gi * 3 + 2] = colors[cb + 2];
                }
            }
        }
    }
}

extern "C" void kernel_launch(void* const* d_in, const int* in_sizes, int n_in,
                              void* d_out, int out_size)
{
    // Identify inputs robustly: x has 2*N elements, p has 700
    int xi = 0, pi = 1;
    if (n_in >= 2 && in_sizes[0] < in_sizes[1]) { xi = 1; pi = 0; }
    const float* x = (const float*)d_in[xi];
    const float* p = (const float*)d_in[pi];
    float* out = (float*)d_out;

    int n = in_sizes[xi] / 2;
    int blocks = (n + TILE - 1) / TILE;
    vg_kernel<<<blocks, TPB>>>(x, p, out, n);
}

// round 11
// speedup vs baseline: 1.1008x; 1.1008x over previous
#include <cuda_runtime.h>

#define TPB  512
#define PPT  4
#define TILE (TPB * PPT)   // 2048 points per block

// Cell record: 5 float4s per cell (25 cells)
//  v0: ax, ay, bx, by
//  v1: cx, cy, d0x(=bx-ax), d0y(=by-ay)
//  v2: d1x(=cx-bx), d1y(=cy-by), d2x(=ax-cx), d2y(=ay-cy)
//  v3: ocx, ocy, r2, ecx
//  v4: ecy, 1/erx, 1/ery, pad

// Shade one cell, update best. Exact reference op order (no fma contraction).
// No validity mask: callers pass a duplicate cell index when a neighbor is
// invalid; re-shading the same cell is idempotent under max().
#define SHADE_CELL(cc)                                                         \
    do {                                                                       \
        int _c = (cc);                                                         \
        float4 v0 = rec[_c * 5 + 0];                                           \
        float4 v1 = rec[_c * 5 + 1];                                           \
        float4 v2 = rec[_c * 5 + 2];                                           \
        float4 v3 = rec[_c * 5 + 3];                                           \
        float4 v4 = rec[_c * 5 + 4];                                           \
        float e0 = __fsub_rn(__fmul_rn(__fsub_rn(px, v0.x), v1.w),             \
                             __fmul_rn(__fsub_rn(py, v0.y), v1.z));            \
        float e1 = __fsub_rn(__fmul_rn(__fsub_rn(px, v0.z), v2.y),             \
                             __fmul_rn(__fsub_rn(py, v0.w), v2.x));            \
        float e2 = __fsub_rn(__fmul_rn(__fsub_rn(px, v1.x), v2.w),             \
                             __fmul_rn(__fsub_rn(py, v1.y), v2.z));            \
        float emin = fminf(fminf(e0, e1), e2);                                 \
        float emax = fmaxf(fmaxf(e0, e1), e2);                                 \
        bool tri_in = (emin >= 0.0f) || (emax <= 0.0f);                        \
        float dxc = __fsub_rn(px, v3.x), dyc = __fsub_rn(py, v3.y);            \
        bool circ_in =                                                         \
            __fadd_rn(__fmul_rn(dxc, dxc), __fmul_rn(dyc, dyc)) <= v3.z;       \
        float xn = __fmul_rn(__fsub_rn(px, v3.w), v4.y);                       \
        float yn = __fmul_rn(__fsub_rn(py, v4.x), v4.z);                       \
        bool ell_in =                                                          \
            __fadd_rn(__fmul_rn(xn, xn), __fmul_rn(yn, yn)) <= 1.0f;           \
        int c3 = _c * 3;                                                       \
        int cb = tri_in ? c3 : -1;                                             \
        cb = circ_in ? c3 + 1 : cb;                                            \
        cb = ell_in ? c3 + 2 : cb;                                             \
        best = best > cb ? best : cb;                                          \
    } while (0)

__global__ __launch_bounds__(TPB, 4)
void vg_kernel(const float* __restrict__ x, const float* __restrict__ p,
               float* __restrict__ out, int n)
{
    __shared__ float4 rec[25 * 5];
    __shared__ float  colors[76 * 3];      // slot 0 = black
    __shared__ float2 sp[TILE];            // (cell,quadrant)-sorted points
    __shared__ unsigned int stmp[TILE];    // key | rank<<8
    __shared__ unsigned int sinfo[TILE];   // orig | key<<11
    __shared__ unsigned char sbest[TILE];  // winner+1 per ORIGINAL point
    __shared__ int hist[225];
    __shared__ int off[225];
    __shared__ int wsum[8];

    const int tid = threadIdx.x;

    if (tid < 25) {
        const float* q = p + tid * 28;
        float ax = q[1], ay = q[2], bx = q[3], by = q[4], cx = q[5], cy = q[6];
        rec[tid * 5 + 0] = make_float4(ax, ay, bx, by);
        rec[tid * 5 + 1] = make_float4(cx, cy, __fsub_rn(bx, ax), __fsub_rn(by, ay));
        rec[tid * 5 + 2] = make_float4(__fsub_rn(cx, bx), __fsub_rn(cy, by),
                                       __fsub_rn(ax, cx), __fsub_rn(ay, cy));
        float ocx = q[12], ocy = q[13], r = q[14];
        float ecx = q[20], ecy = q[21], erx = q[22], ery = q[23];
        rec[tid * 5 + 3] = make_float4(ocx, ocy, __fmul_rn(r, r), ecx);
        rec[tid * 5 + 4] = make_float4(ecy, 1.0f / erx, 1.0f / ery, 0.0f);
    }
    for (int idx = tid; idx < 228; idx += TPB) {
        if (idx < 3) colors[idx] = 0.0f;
        else {
            int s = (idx - 3) / 3, k = (idx - 3) % 3;
            int c = s / 3, t = s % 3;
            int o = (t == 0) ? (8 + k) : ((t == 1) ? (16 + k) : (25 + k));
            colors[idx] = p[c * 28 + o];
        }
    }
    if (tid < 225) hist[tid] = 0;
    __syncthreads();

    const int base = blockIdx.x * TILE;

    // ---- Phase 1: load points, integer classify, histogram ----
    float2 pts[PPT];
#pragma unroll
    for (int k = 0; k < PPT; k++) {
        int li = k * TPB + tid;
        int gi = base + li;
        float2 pt = (gi < n) ? ((const float2*)x)[gi] : make_float2(0.5f, 0.5f);
        pts[k] = pt;
        // 1/16-cell units; neighbor needed only for overhang < 0.4 cell,
        // thresholds 7/16 / 9/16 bracket it with >=0.0375 cell margin.
        int sx = (int)(pt.x * 80.0f); sx = sx < 0 ? 0 : (sx > 79 ? 79 : sx);
        int sy = (int)(pt.y * 80.0f); sy = sy < 0 ? 0 : (sy > 79 ? 79 : sy);
        int ci = sx >> 4, fx = sx & 15;
        int cj = sy >> 4, fy = sy & 15;
        int dxp = (fx <= 6) ? 0 : ((fx >= 9) ? 2 : 1);   // dxn+1
        int dyp = (fy <= 6) ? 0 : ((fy >= 9) ? 2 : 1);   // dyn+1
        int key = (ci * 5 + cj) * 9 + dxp * 3 + dyp;     // 0..224
        int rank = atomicAdd(&hist[key], 1);
        stmp[li] = (unsigned)key | ((unsigned)rank << 8);
    }
    __syncthreads();

    // ---- Phase 2: exclusive scan of 225 bins (warps 0-7 only) ----
    {
        int v = 0, s = 0;
        if (tid < 256) {
            v = (tid < 225) ? hist[tid] : 0;
            s = v;
#pragma unroll
            for (int d = 1; d < 32; d <<= 1) {
                int t = __shfl_up_sync(0xffffffff, s, d);
                if ((tid & 31) >= d) s += t;
            }
            if ((tid & 31) == 31) wsum[tid >> 5] = s;
        }
        __syncthreads();
        if (tid < 8) {
            int w = wsum[tid];
            int sw = w;
#pragma unroll
            for (int d = 1; d < 8; d <<= 1) {
                int t = __shfl_up_sync(0xff, sw, d);
                if (tid >= d) sw += t;
            }
            wsum[tid] = sw - w;
        }
        __syncthreads();
        if (tid < 225) off[tid] = (s - v) + wsum[tid >> 5];
    }
    __syncthreads();

    // ---- Phase 3: scatter into (cell,quadrant)-sorted order ----
#pragma unroll
    for (int k = 0; k < PPT; k++) {
        int li = k * TPB + tid;
        unsigned m = stmp[li];
        unsigned key = m & 255;
        int pos = off[key] + (int)(m >> 8);
        sp[pos]    = pts[k];
        sinfo[pos] = (unsigned)li | (key << 11);
    }
    __syncthreads();

    // ---- Phase 4: uniform 4-cell shading (dup-clamped, no masks) ----
#pragma unroll 1
    for (int k = 0; k < PPT; k++) {
        int li = k * TPB + tid;
        float2 pt = sp[li];
        const float px = pt.x, py = pt.y;
        unsigned m = sinfo[li];
        int orig = m & 2047;
        int key  = (int)(m >> 11);
        int cc   = key / 9;
        int rem  = key - cc * 9;
        int dxp  = rem / 3;
        int dyn  = (rem - dxp * 3) - 1;
        int dxn  = dxp - 1;
        int ci   = cc / 5;
        int cj   = cc - ci * 5;
        int i2 = ci + dxn, j2 = cj + dyn;
        int ccx = ((unsigned)i2 <= 4u) ? cc + dxn * 5 : cc;   // dup if off-grid
        int ccy = ((unsigned)j2 <= 4u) ? cc + dyn     : cc;
        int ccxy = ccx + (ccy - cc);

        int best = -1;
        SHADE_CELL(cc);
        SHADE_CELL(ccx);
        SHADE_CELL(ccy);
        SHADE_CELL(ccxy);

        sbest[orig] = (unsigned char)(best + 1);
    }
    __syncthreads();

    // ---- Phase 5: output in original order ----
#pragma unroll
    for (int k = 0; k < PPT; k++) {
        int li = k * TPB + tid;
        int gi = base + li;
        if (gi < n) {
            int cb = (int)sbest[li] * 3;
            out[gi * 3 + 0] = colors[cb + 0];
            out[gi * 3 + 1] = colors[cb + 1];
            out[gi * 3 + 2] = colors[cb + 2];
        }
    }
}

extern "C" void kernel_launch(void* const* d_in, const int* in_sizes, int n_in,
                              void* d_out, int out_size)
{
    // Identify inputs robustly: x has 2*N elements, p has 700
    int xi = 0, pi = 1;
    if (n_in >= 2 && in_sizes[0] < in_sizes[1]) { xi = 1; pi = 0; }
    const float* x = (const float*)d_in[xi];
    const float* p = (const float*)d_in[pi];
    float* out = (float*)d_out;

    int n = in_sizes[xi] / 2;
    int blocks = (n + TILE - 1) / TILE;
    vg_kernel<<<blocks, TPB>>>(x, p, out, n);
}

// round 12
// speedup vs baseline: 1.1416x; 1.0370x over previous
#include <cuda_runtime.h>

#define TPB  256
#define PPT  4
#define TILE (TPB * PPT)   // 1024 points per block

// Cell record (13 floats): 3 x float4 + 1 scalar
//  r0: ax, ay, bx, by
//  r1: cx, cy, ocx, ocy
//  r2: r*r, ecx, ecy, 1/erx
//  siery: 1/ery
// Edge deltas recomputed in registers with bit-identical __fsub_rn.

// Shade one cell, update best. Exact reference op order (no fma contraction).
// No validity mask: caller passes a duplicate cell when a neighbor is
// off-grid; re-shading the same cell is idempotent under max().
#define SHADE_CELL(cell)                                                       \
    do {                                                                       \
        int _c = (cell);                                                       \
        float4 r0  = rec4[_c * 3 + 0];                                         \
        float4 r1  = rec4[_c * 3 + 1];                                         \
        float4 r2v = rec4[_c * 3 + 2];                                         \
        float  iery = siery[_c];                                               \
        float d0x = __fsub_rn(r0.z, r0.x), d0y = __fsub_rn(r0.w, r0.y);        \
        float d1x = __fsub_rn(r1.x, r0.z), d1y = __fsub_rn(r1.y, r0.w);        \
        float d2x = __fsub_rn(r0.x, r1.x), d2y = __fsub_rn(r0.y, r1.y);        \
        float e0 = __fsub_rn(__fmul_rn(__fsub_rn(px, r0.x), d0y),              \
                             __fmul_rn(__fsub_rn(py, r0.y), d0x));             \
        float e1 = __fsub_rn(__fmul_rn(__fsub_rn(px, r0.z), d1y),              \
                             __fmul_rn(__fsub_rn(py, r0.w), d1x));             \
        float e2 = __fsub_rn(__fmul_rn(__fsub_rn(px, r1.x), d2y),              \
                             __fmul_rn(__fsub_rn(py, r1.y), d2x));             \
        float emin = fminf(fminf(e0, e1), e2);                                 \
        float emax = fmaxf(fmaxf(e0, e1), e2);                                 \
        bool tri_in = (emin >= 0.0f) || (emax <= 0.0f);                        \
        float dcx = __fsub_rn(px, r1.z), dcy = __fsub_rn(py, r1.w);            \
        bool circ_in =                                                         \
            __fadd_rn(__fmul_rn(dcx, dcx), __fmul_rn(dcy, dcy)) <= r2v.x;      \
        float xn = __fmul_rn(__fsub_rn(px, r2v.y), r2v.w);                     \
        float yn = __fmul_rn(__fsub_rn(py, r2v.z), iery);                      \
        bool ell_in =                                                          \
            __fadd_rn(__fmul_rn(xn, xn), __fmul_rn(yn, yn)) <= 1.0f;           \
        int c3 = _c * 3;                                                       \
        int cb = tri_in ? c3 : -1;                                             \
        cb = circ_in ? c3 + 1 : cb;                                            \
        cb = ell_in ? c3 + 2 : cb;                                             \
        best = best > cb ? best : cb;                                          \
    } while (0)

__global__ __launch_bounds__(TPB, 8)
void vg_kernel(const float* __restrict__ x, const float* __restrict__ p,
               float* __restrict__ out, int n)
{
    __shared__ float4 rec4[25 * 3];
    __shared__ float  siery[25];
    __shared__ float  colors[76 * 3];      // slot 0 = black
    __shared__ float2 sp[TILE];            // (cell,quadrant)-sorted points
    __shared__ unsigned int stmp[TILE];    // key | rank<<8 | meta<<18
    __shared__ unsigned int sinfo[TILE];   // orig | meta<<10
    __shared__ unsigned char sbest[TILE];  // winner+1 per ORIGINAL point
    __shared__ int hist[225];
    __shared__ int off[225];
    __shared__ int wsum[8];

    const int tid = threadIdx.x;

    if (tid < 25) {
        const float* q = p + tid * 28;
        rec4[tid * 3 + 0] = make_float4(q[1], q[2], q[3], q[4]);
        rec4[tid * 3 + 1] = make_float4(q[5], q[6], q[12], q[13]);
        rec4[tid * 3 + 2] = make_float4(__fmul_rn(q[14], q[14]),
                                        q[20], q[21], 1.0f / q[22]);
        siery[tid] = 1.0f / q[23];
    }
    for (int idx = tid; idx < 228; idx += TPB) {
        if (idx < 3) colors[idx] = 0.0f;
        else {
            int s = (idx - 3) / 3, k = (idx - 3) % 3;
            int c = s / 3, t = s % 3;
            int o = (t == 0) ? (8 + k) : ((t == 1) ? (16 + k) : (25 + k));
            colors[idx] = p[c * 28 + o];
        }
    }
    if (tid < 225) hist[tid] = 0;
    __syncthreads();

    const int base = blockIdx.x * TILE;

    // ---- Phase 1: load points, integer classify, histogram ----
    float2 pts[PPT];
#pragma unroll
    for (int k = 0; k < PPT; k++) {
        int li = k * TPB + tid;
        int gi = base + li;
        float2 pt = (gi < n) ? ((const float2*)x)[gi] : make_float2(0.5f, 0.5f);
        pts[k] = pt;
        // 1/16-cell fixed point. Neighbor needed only when the point is
        // within 0.4 cell-widths of a boundary; thresholds 7/16 and 9/16
        // bracket that with >=0.0375cw margin (>> any f32 rounding).
        int sx = (int)(pt.x * 80.0f); sx = sx < 0 ? 0 : (sx > 79 ? 79 : sx);
        int sy = (int)(pt.y * 80.0f); sy = sy < 0 ? 0 : (sy > 79 ? 79 : sy);
        int ci = sx >> 4, fx = sx & 15;
        int cj = sy >> 4, fy = sy & 15;
        int dxp = (fx <= 6) ? 0 : ((fx >= 9) ? 2 : 1);   // dxn+1
        int dyp = (fy <= 6) ? 0 : ((fy >= 9) ? 2 : 1);   // dyn+1
        int cc  = ci * 5 + cj;
        int key = cc * 9 + dxp * 3 + dyp;                // 0..224
        unsigned vx = (dxp != 1) && ((unsigned)(ci + dxp - 1) <= 4u);
        unsigned vy = (dyp != 1) && ((unsigned)(cj + dyp - 1) <= 4u);
        unsigned meta = (unsigned)cc | ((unsigned)dxp << 5) |
                        ((unsigned)dyp << 7) | (vx << 9) | (vy << 10);
        int rank = atomicAdd(&hist[key], 1);
        stmp[li] = (unsigned)key | ((unsigned)rank << 8) | (meta << 18);
    }
    __syncthreads();

    // ---- Phase 2: exclusive scan of 225 bins (two-level shuffle scan) ----
    {
        int v = (tid < 225) ? hist[tid] : 0;
        int s = v;
#pragma unroll
        for (int d = 1; d < 32; d <<= 1) {
            int t = __shfl_up_sync(0xffffffff, s, d);
            if ((tid & 31) >= d) s += t;
        }
        if ((tid & 31) == 31) wsum[tid >> 5] = s;
        __syncthreads();
        if (tid < 8) {
            int w = wsum[tid];
            int sw = w;
#pragma unroll
            for (int d = 1; d < 8; d <<= 1) {
                int t = __shfl_up_sync(0xff, sw, d);
                if (tid >= d) sw += t;
            }
            wsum[tid] = sw - w;
        }
        __syncthreads();
        if (tid < 225) off[tid] = (s - v) + wsum[tid >> 5];
    }
    __syncthreads();

    // ---- Phase 3: scatter into (cell,quadrant)-sorted order ----
#pragma unroll
    for (int k = 0; k < PPT; k++) {
        int li = k * TPB + tid;
        unsigned m = stmp[li];
        int pos = off[m & 255] + (int)((m >> 8) & 1023);
        sp[pos]    = pts[k];
        sinfo[pos] = (unsigned)li | ((m >> 18) << 10);
    }
    __syncthreads();

    // ---- Phase 4: uniform 4-cell shading (dup-clamped, flat) ----
#pragma unroll 1
    for (int k = 0; k < PPT; k++) {
        int li = k * TPB + tid;
        float2 pt = sp[li];
        const float px = pt.x, py = pt.y;
        unsigned m = sinfo[li];
        int orig = m & 1023;
        int cc   = (m >> 10) & 31;
        int dxn  = (int)((m >> 15) & 3) - 1;
        int dyn  = (int)((m >> 17) & 3) - 1;
        int ccx  = ((m >> 19) & 1) ? cc + dxn * 5 : cc;   // dup if off-grid
        int ccy  = ((m >> 20) & 1) ? cc + dyn     : cc;
        int ccxy = ccx + (ccy - cc);

        int best = -1;
        SHADE_CELL(cc);
        SHADE_CELL(ccx);
        SHADE_CELL(ccy);
        SHADE_CELL(ccxy);

        sbest[orig] = (unsigned char)(best + 1);
    }
    __syncthreads();

    // ---- Phase 5: output in original order ----
#pragma unroll
    for (int k = 0; k < PPT; k++) {
        int li = k * TPB + tid;
        int gi = base + li;
        if (gi < n) {
            int cb = (int)sbest[li] * 3;
            out[gi * 3 + 0] = colors[cb + 0];
            out[gi * 3 + 1] = colors[cb + 1];
            out[gi * 3 + 2] = colors[cb + 2];
        }
    }
}

extern "C" void kernel_launch(void* const* d_in, const int* in_sizes, int n_in,
                              void* d_out, int out_size)
{
    // Identify inputs robustly: x has 2*N elements, p has 700
    int xi = 0, pi = 1;
    if (n_in >= 2 && in_sizes[0] < in_sizes[1]) { xi = 1; pi = 0; }
    const float* x = (const float*)d_in[xi];
    const float* p = (const float*)d_in[pi];
    float* out = (float*)d_out;

    int n = in_sizes[xi] / 2;
    int blocks = (n + TILE - 1) / TILE;
    vg_kernel<<<blocks, TPB>>>(x, p, out, n);
}